// round 1
// baseline (speedup 1.0000x reference)
#include <cuda_runtime.h>
#include <cuda_bf16.h>
#include <math.h>

// ---------------------------------------------------------------------------
// MnistAdditionModule: LeNet (16384 digit images) -> per-digit log-softmax
//                      -> circuit over n1+n2 sums  => out [4096, 199] fp32
// ---------------------------------------------------------------------------

#define N_IMAGES 16384
#define BATCH    4096

// intermediate buffers (static device memory; no allocations allowed)
__device__ float g_out1[N_IMAGES * 6 * 12 * 12];   // conv1+pool+relu
__device__ float g_out2[N_IMAGES * 256];           // conv2+pool+relu (flattened)
__device__ float g_lp  [N_IMAGES * 10];            // per-image log-probs

// ---------------------------------------------------------------------------
// K1: conv1 (1->6, 5x5, valid) + bias + maxpool2 + relu.  One block per image.
// ---------------------------------------------------------------------------
__global__ void conv1_kernel(const float* __restrict__ images,
                             const float* __restrict__ w,
                             const float* __restrict__ b) {
    __shared__ float img[784];
    __shared__ float ws[150];
    __shared__ float bs[6];
    int n = blockIdx.x;
    const float* im = images + n * 784;
    for (int i = threadIdx.x; i < 784; i += blockDim.x) img[i] = im[i];
    if (threadIdx.x < 150) ws[threadIdx.x] = w[threadIdx.x];
    if (threadIdx.x < 6)   bs[threadIdx.x] = b[threadIdx.x];
    __syncthreads();

    int t = threadIdx.x;
    if (t >= 144) return;
    int oh = t / 12, ow = t - oh * 12;

    // 6x6 input window covering the 2x2 pooled conv outputs
    float win[6][6];
#pragma unroll
    for (int i = 0; i < 6; i++)
#pragma unroll
        for (int j = 0; j < 6; j++)
            win[i][j] = img[(2 * oh + i) * 28 + (2 * ow + j)];

    float* out = g_out1 + n * 864 + t;
#pragma unroll
    for (int ch = 0; ch < 6; ch++) {
        float a00 = 0.f, a01 = 0.f, a10 = 0.f, a11 = 0.f;
        const float* wp = &ws[ch * 25];
#pragma unroll
        for (int i = 0; i < 5; i++)
#pragma unroll
            for (int j = 0; j < 5; j++) {
                float wv = wp[i * 5 + j];
                a00 = fmaf(win[i][j],     wv, a00);
                a01 = fmaf(win[i][j + 1], wv, a01);
                a10 = fmaf(win[i + 1][j],     wv, a10);
                a11 = fmaf(win[i + 1][j + 1], wv, a11);
            }
        float m = fmaxf(fmaxf(a00, a01), fmaxf(a10, a11)) + bs[ch];
        out[ch * 144] = fmaxf(m, 0.f);
    }
}

// ---------------------------------------------------------------------------
// K2: conv2 (6->16, 5x5, valid on 12x12) + bias + maxpool2 + relu.
// One block (256 threads) per image; thread t -> ch=t/16, pooled pos=t%16.
// ---------------------------------------------------------------------------
__global__ void conv2_kernel(const float* __restrict__ w,
                             const float* __restrict__ b) {
    __shared__ float in[864];    // 6 x 12 x 12
    __shared__ float ws[2400];   // 16 x 6 x 25
    __shared__ float bs[16];
    int n = blockIdx.x;
    for (int i = threadIdx.x; i < 864; i += 256)  in[i] = g_out1[n * 864 + i];
    for (int i = threadIdx.x; i < 2400; i += 256) ws[i] = w[i];
    if (threadIdx.x < 16) bs[threadIdx.x] = b[threadIdx.x];
    __syncthreads();

    int t  = threadIdx.x;
    int ch = t >> 4, pos = t & 15;
    int oh = pos >> 2, ow = pos & 3;

    float a00 = 0.f, a01 = 0.f, a10 = 0.f, a11 = 0.f;
#pragma unroll
    for (int ic = 0; ic < 6; ic++) {
        float win[6][6];
#pragma unroll
        for (int i = 0; i < 6; i++)
#pragma unroll
            for (int j = 0; j < 6; j++)
                win[i][j] = in[ic * 144 + (2 * oh + i) * 12 + (2 * ow + j)];
        const float* wp = &ws[(ch * 6 + ic) * 25];
#pragma unroll
        for (int i = 0; i < 5; i++)
#pragma unroll
            for (int j = 0; j < 5; j++) {
                float wv = wp[i * 5 + j];
                a00 = fmaf(win[i][j],     wv, a00);
                a01 = fmaf(win[i][j + 1], wv, a01);
                a10 = fmaf(win[i + 1][j],     wv, a10);
                a11 = fmaf(win[i + 1][j + 1], wv, a11);
            }
    }
    float m = fmaxf(fmaxf(a00, a01), fmaxf(a10, a11)) + bs[ch];
    // flattened feature index c*16 + h*4 + w == t  (NCHW reshape)
    g_out2[n * 256 + t] = fmaxf(m, 0.f);
}

// ---------------------------------------------------------------------------
// K3: fc1(256->120)+relu, fc2(120->84)+relu, fc3(84->10), log_softmax.
// All weights resident in smem (k-major so lane-j reads are conflict-free).
// 16 images per block, 1024 blocks.
// ---------------------------------------------------------------------------
#define FC_SMEM_FLOATS (30720 + 10080 + 840 + 120 + 84 + 16 + 4096 + 1920 + 1344 + 160)
#define FC_SMEM_BYTES  (FC_SMEM_FLOATS * 4)

__global__ void fc_kernel(const float* __restrict__ w1, const float* __restrict__ b1,
                          const float* __restrict__ w2, const float* __restrict__ b2,
                          const float* __restrict__ w3, const float* __restrict__ b3) {
    extern __shared__ float sm[];
    float* s_w1 = sm;              // [256][120] (k-major)
    float* s_w2 = s_w1 + 30720;    // [120][84]
    float* s_w3 = s_w2 + 10080;    // [84][10]
    float* s_b1 = s_w3 + 840;      // 120
    float* s_b2 = s_b1 + 120;      // 84
    float* s_b3 = s_b2 + 84;       // 10 (padded to 16)
    float* s_x  = s_b3 + 16;       // [16][256]
    float* s_h1 = s_x  + 4096;     // [16][120]
    float* s_h2 = s_h1 + 1920;     // [16][84]
    float* s_z  = s_h2 + 1344;     // [16][10]

    int t = threadIdx.x;           // 256 threads
    // load weights, transposed to k-major
    for (int i = t; i < 30720; i += 256)
        s_w1[(i & 255) * 120 + (i >> 8)] = w1[i];          // i = j*256 + k
    for (int i = t; i < 10080; i += 256) {
        int j = i / 120, k = i - j * 120;
        s_w2[k * 84 + j] = w2[i];
    }
    for (int i = t; i < 840; i += 256) {
        int j = i / 84, k = i - j * 84;
        s_w3[k * 10 + j] = w3[i];
    }
    if (t < 120) s_b1[t] = b1[t];
    if (t < 84)  s_b2[t] = b2[t];
    if (t < 10)  s_b3[t] = b3[t];

    int n0 = blockIdx.x * 16;
    for (int i = t; i < 4096; i += 256) s_x[i] = g_out2[n0 * 256 + i];
    __syncthreads();

    // fc1: 16*120 = 1920 dots over 256
    for (int o = t; o < 1920; o += 256) {
        int g = o / 120, j = o - g * 120;
        const float* xp = s_x + g * 256;
        float acc = s_b1[j];
#pragma unroll 8
        for (int k = 0; k < 256; k++) acc = fmaf(xp[k], s_w1[k * 120 + j], acc);
        s_h1[g * 120 + j] = fmaxf(acc, 0.f);
    }
    __syncthreads();

    // fc2: 16*84 = 1344 dots over 120
    for (int o = t; o < 1344; o += 256) {
        int g = o / 84, j = o - g * 84;
        const float* xp = s_h1 + g * 120;
        float acc = s_b2[j];
#pragma unroll 8
        for (int k = 0; k < 120; k++) acc = fmaf(xp[k], s_w2[k * 84 + j], acc);
        s_h2[g * 84 + j] = fmaxf(acc, 0.f);
    }
    __syncthreads();

    // fc3: 16*10 = 160 dots over 84
    for (int o = t; o < 160; o += 256) {
        int g = o / 10, j = o - g * 10;
        const float* xp = s_h2 + g * 84;
        float acc = s_b3[j];
#pragma unroll
        for (int k = 0; k < 84; k++) acc = fmaf(xp[k], s_w3[k * 10 + j], acc);
        s_z[o] = acc;
    }
    __syncthreads();

    // log_softmax per image
    if (t < 16) {
        const float* z = s_z + t * 10;
        float m = -1e30f;
#pragma unroll
        for (int i = 0; i < 10; i++) m = fmaxf(m, z[i]);
        float s = 0.f;
#pragma unroll
        for (int i = 0; i < 10; i++) s += __expf(z[i] - m);
        float lse = __logf(s) + m;
        float* out = g_lp + (n0 + t) * 10;
#pragma unroll
        for (int i = 0; i < 10; i++) out[i] = z[i] - lse;
    }
}

// ---------------------------------------------------------------------------
// K4: circuit. For each batch element b:
//   lp1[k] = lp[d0][k/10] + lp[d1][k%10]  (k = 0..99), same for lp2.
//   out[s] = logsumexp_{i+j=s}(lp1[i]+lp2[j])
// Computed as a linear-space convolution of the max-normalized prob vectors:
//   out[s] = log( sum_i p1[i]*p2[s-i] ) + m1 + m2   (exactly equivalent)
// ---------------------------------------------------------------------------
__global__ void circuit_kernel(float* __restrict__ out) {
    __shared__ float p1[100], p2[100];
    __shared__ float msum[2];
    int b = blockIdx.x;
    const float* lp = g_lp + b * 40;
    int t = threadIdx.x;   // 256 threads

    if (t == 0) {
        float m0 = -1e30f, m1 = -1e30f, m2 = -1e30f, m3 = -1e30f;
#pragma unroll
        for (int i = 0; i < 10; i++) {
            m0 = fmaxf(m0, lp[i]);
            m1 = fmaxf(m1, lp[10 + i]);
            m2 = fmaxf(m2, lp[20 + i]);
            m3 = fmaxf(m3, lp[30 + i]);
        }
        msum[0] = m0 + m1;
        msum[1] = m2 + m3;
    }
    __syncthreads();
    if (t < 100) {
        p1[t] = __expf(lp[t / 10] + lp[10 + t % 10] - msum[0]);
    } else if (t < 200) {
        int k = t - 100;
        p2[k] = __expf(lp[20 + k / 10] + lp[30 + k % 10] - msum[1]);
    }
    __syncthreads();
    if (t < 199) {
        int lo = max(0, t - 99), hi = min(99, t);
        float s = 0.f;
        for (int i = lo; i <= hi; i++) s = fmaf(p1[i], p2[t - i], s);
        out[b * 199 + t] = __logf(s) + msum[0] + msum[1];
    }
}

// ---------------------------------------------------------------------------
extern "C" void kernel_launch(void* const* d_in, const int* in_sizes, int n_in,
                              void* d_out, int out_size) {
    const float* images = (const float*)d_in[0];
    const float* c1w    = (const float*)d_in[1];
    const float* c1b    = (const float*)d_in[2];
    const float* c2w    = (const float*)d_in[3];
    const float* c2b    = (const float*)d_in[4];
    const float* f1w    = (const float*)d_in[5];
    const float* f1b    = (const float*)d_in[6];
    const float* f2w    = (const float*)d_in[7];
    const float* f2b    = (const float*)d_in[8];
    const float* f3w    = (const float*)d_in[9];
    const float* f3b    = (const float*)d_in[10];
    float* out = (float*)d_out;

    cudaFuncSetAttribute(fc_kernel, cudaFuncAttributeMaxDynamicSharedMemorySize,
                         FC_SMEM_BYTES);

    conv1_kernel<<<N_IMAGES, 160>>>(images, c1w, c1b);
    conv2_kernel<<<N_IMAGES, 256>>>(c2w, c2b);
    fc_kernel<<<N_IMAGES / 16, 256, FC_SMEM_BYTES>>>(f1w, f1b, f2w, f2b, f3w, f3b);
    circuit_kernel<<<BATCH, 256>>>(out);
}